// round 12
// baseline (speedup 1.0000x reference)
#include <cuda_runtime.h>
#include <cstdint>

#define B_   16
#define CIN  32
#define COUT 64
#define H_   16
#define W_   512
#define LRELU_SLOPE 0.3f
#define BN_EPS 1e-5f

typedef unsigned long long u64;
typedef unsigned int u32;

__device__ __forceinline__ void fma2(u64 &d, u64 a, u64 b) {
    asm("fma.rn.f32x2 %0,%1,%2,%0;" : "+l"(d) : "l"(a), "l"(b));
}
__device__ __forceinline__ void upk(u64 v, float &lo, float &hi) {
    asm("mov.b64 {%0,%1},%2;" : "=f"(lo), "=f"(hi) : "l"(v));
}
__device__ __forceinline__ u64 pk2(float lo, float hi) {
    u64 r; asm("mov.b64 %0,{%1,%2};" : "=l"(r) : "f"(lo), "f"(hi)); return r;
}
__device__ __forceinline__ u64 dup2(float v) {
    u64 r; asm("mov.b64 %0,{%1,%1};" : "=l"(r) : "f"(v)); return r;
}
// pack (lo,hi) floats -> bf16x2 (lo in low 16 bits)
__device__ __forceinline__ u32 bfpair(float lo, float hi) {
    u32 r; asm("cvt.rn.satfinite.bf16x2.f32 %0, %1, %2;" : "=r"(r) : "f"(hi), "f"(lo)); return r;
}
__device__ __forceinline__ u32 smem_u32_of(const void* p) {
    u32 a; asm("{ .reg .u64 t; cvta.to.shared.u64 t, %1; cvt.u32.u64 %0, t; }" : "=r"(a) : "l"(p));
    return a;
}

// ---- SMEM layout (float offsets) ----
#define SQ_OFF   0                    // Q  16x512 fp32
#define SK_OFF   8192                 // K  16x512 fp32
#define SV_OFF   16384                // V  16x512 fp32
#define SCR_OFF  24576                // union: conv staging 32x520 (16640) | A bf16 3x(32 rows x 1024B swz)
#define SVN_OFF  49152                // Vn bf16 2x(16x80B) = 640 fl
#define SSUM     49792                // 2 x [32 w-rows][4 warp-partials]
#define SWOFF    50048                // weights [4t][32ci][12] dup'd
#define SBIAS    51584
#define SMEM_FLOATS 51588
#define SMEM_BYTES  (SMEM_FLOATS * 4) // 206352 B

#define SCR_BYTE 98304                // = SCR_OFF*4 (1024-aligned)
#define SVN_BYTE 196608               // = SVN_OFF*4

#define XROW 520

__global__ __launch_bounds__(512, 1)
void conv_attn_fused_kernel(
    const float* __restrict__ x,
    const float* __restrict__ wq, const float* __restrict__ gq, const float* __restrict__ bq, const float* __restrict__ mq, const float* __restrict__ vq,
    const float* __restrict__ wk, const float* __restrict__ gk, const float* __restrict__ bk, const float* __restrict__ mk, const float* __restrict__ vk,
    const float* __restrict__ wv, const float* __restrict__ gv, const float* __restrict__ bv, const float* __restrict__ mv, const float* __restrict__ vv,
    const float* __restrict__ wp, const float* __restrict__ gp, const float* __restrict__ bp, const float* __restrict__ mp, const float* __restrict__ vp,
    float* __restrict__ out)
{
    extern __shared__ float sm[];
    char* smb = (char*)sm;
    const int bid = blockIdx.x;
    const int b   = bid >> 6;
    const int c   = bid & 63;
    const int tid = threadIdx.x;
    const int warp = tid >> 5, lane = tid & 31;
    const u32 smem0 = smem_u32_of(sm);
    float* og = out + (size_t)bid * (H_ * W_);

    // ---------------- BN-folded weights, duplicated taps ----------------
    if (tid < 160) {
        const int ci = tid / 5, kk = tid - ci * 5;
        const int src = c * 160 + ci * 5 + kk;
        const int dst = ci * 12 + 2 * kk;
        float s, a;
        s = gq[c] * rsqrtf(vq[c] + BN_EPS); a = wq[src] * s;
        sm[SWOFF + 0*384 + dst] = a; sm[SWOFF + 0*384 + dst + 1] = a;
        s = gk[c] * rsqrtf(vk[c] + BN_EPS); a = wk[src] * s;
        sm[SWOFF + 1*384 + dst] = a; sm[SWOFF + 1*384 + dst + 1] = a;
        s = gv[c] * rsqrtf(vv[c] + BN_EPS); a = wv[src] * s;
        sm[SWOFF + 2*384 + dst] = a; sm[SWOFF + 2*384 + dst + 1] = a;
        s = gp[c] * rsqrtf(vp[c] + BN_EPS); a = wp[src] * s;
        sm[SWOFF + 3*384 + dst] = a; sm[SWOFF + 3*384 + dst + 1] = a;
    }
    if (tid == 0) {
        float s;
        s = gq[c] * rsqrtf(vq[c] + BN_EPS); sm[SBIAS + 0] = bq[c] - mq[c] * s;
        s = gk[c] * rsqrtf(vk[c] + BN_EPS); sm[SBIAS + 1] = bk[c] - mk[c] * s;
        s = gv[c] * rsqrtf(vv[c] + BN_EPS); sm[SBIAS + 2] = bv[c] - mv[c] * s;
        s = gp[c] * rsqrtf(vp[c] + BN_EPS); sm[SBIAS + 3] = bp[c] - mp[c] * s;
    }
    if (tid < 128) {   // zero staging halos {2,3,516,517} per row
        int row = tid >> 2, q4 = tid & 3;
        int off = (q4 < 2) ? (2 + q4) : (514 + q4);
        sm[SCR_OFF + row * XROW + off] = 0.0f;
    }

    // ---------------- Conv(1x5)+BN+LeakyReLU : 8h x 8w tiles, 2 passes (R10, verified) ----
    const int hgrp = tid >> 6;
    const int w0c  = (tid & 63) << 3;
    const float* xb = x + (size_t)b * CIN * H_ * W_;

    for (int hb = 0; hb < 2; hb++) {
        u64 acc2[4][4];
        #pragma unroll
        for (int t = 0; t < 4; t++)
            #pragma unroll
            for (int j = 0; j < 4; j++) acc2[t][j] = 0ull;

        for (int cib = 0; cib < 8; cib++) {
            float4 stg[8];
            #pragma unroll
            for (int it = 0; it < 8; it++) {
                int i  = tid + (it << 9);
                int ci = i >> 10, hh = (i >> 7) & 7, w4 = (i & 127) << 2;
                stg[it] = *(const float4*)&xb[(((size_t)(cib*4 + ci)) * H_ + (hb*8 + hh)) * W_ + w4];
            }
            __syncthreads();
            #pragma unroll
            for (int it = 0; it < 8; it++) {
                int i  = tid + (it << 9);
                int ci = i >> 10, hh = (i >> 7) & 7, w4 = (i & 127) << 2;
                *(float4*)&sm[SCR_OFF + (ci*8 + hh) * XROW + 4 + w4] = stg[it];
            }
            __syncthreads();

            #pragma unroll
            for (int ci4 = 0; ci4 < 4; ci4++) {
                const float* xr = &sm[SCR_OFF + (ci4*8 + hgrp) * XROW + w0c];
                float4 f0 = *(const float4*)(xr);
                float4 f1 = *(const float4*)(xr + 4);
                float4 f2 = *(const float4*)(xr + 8);
                float4 f3 = *(const float4*)(xr + 12);
                float xm[16] = {f0.x,f0.y,f0.z,f0.w, f1.x,f1.y,f1.z,f1.w,
                                f2.x,f2.y,f2.z,f2.w, f3.x,f3.y,f3.z,f3.w};
                u64 P[11];
                #pragma unroll
                for (int n = 0; n < 11; n++) P[n] = pk2(xm[n+2], xm[n+3]);
                const int cig = cib*4 + ci4;
                #pragma unroll
                for (int t = 0; t < 4; t++) {
                    const float* wr = &sm[SWOFF + t*384 + cig*12];
                    ulonglong2 wa = *(const ulonglong2*)wr;
                    ulonglong2 wb2 = *(const ulonglong2*)(wr + 4);
                    u64 wc = *(const u64*)(wr + 8);
                    u64 w5[5] = { wa.x, wa.y, wb2.x, wb2.y, wc };
                    #pragma unroll
                    for (int kk2 = 0; kk2 < 5; kk2++)
                        #pragma unroll
                        for (int jp = 0; jp < 4; jp++)
                            fma2(acc2[t][jp], P[2*jp + kk2], w5[kk2]);
                }
            }
        }
        const int h = hb*8 + hgrp;
        #pragma unroll
        for (int t = 0; t < 4; t++) {
            float bias = sm[SBIAS + t];
            float y[8];
            #pragma unroll
            for (int jp = 0; jp < 4; jp++) {
                float lo, hi; upk(acc2[t][jp], lo, hi);
                y[2*jp]   = lo + bias;
                y[2*jp+1] = hi + bias;
            }
            #pragma unroll
            for (int j = 0; j < 8; j++) y[j] = (y[j] >= 0.f) ? y[j] : LRELU_SLOPE * y[j];
            if (t == 3) {
                // PE straight to gmem (read back in epilogue; L2-resident)
                *(float4*)&og[h * W_ + w0c]     = make_float4(y[0], y[1], y[2], y[3]);
                *(float4*)&og[h * W_ + w0c + 4] = make_float4(y[4], y[5], y[6], y[7]);
            } else {
                float* d = (t == 0) ? (sm + SQ_OFF + h * W_ + w0c)
                         : (t == 1) ? (sm + SK_OFF + h * W_ + w0c)
                                    : (sm + SV_OFF + h * W_ + w0c);
                *(float4*)(d)     = make_float4(y[0], y[1], y[2], y[3]);
                *(float4*)(d + 4) = make_float4(y[4], y[5], y[6], y[7]);
            }
        }
    }
    __syncthreads();   // Q/K/V ready; staging area becomes A triple-buffer

    // -------- Attention: 3-stage pipeline, ONE barrier per interval --------
    // X_i = { prod(i) || Vnb(i-1) || cons(i-2) } ; A mod-3, Vn/psums mod-2
    const int rgrpS = tid >> 7;           // 0..3 : S rows rgrpS*8..+7 (w-rows)
    const int v4    = (tid & 127) << 2;   // 4 v-cols
    const int wslot = warp & 3;
    const int agrp = lane >> 3, alr = lane & 7;
    const int a_voff = (agrp & 1) << 3;
    const int a_roff = (agrp >> 1) << 3;

    float acc[2][2][4];                   // consume D[v][h] fragments
    #pragma unroll
    for (int mi = 0; mi < 2; mi++)
        #pragma unroll
        for (int ni = 0; ni < 2; ni++)
            #pragma unroll
            for (int q = 0; q < 4; q++) acc[mi][ni][q] = 0.0f;

    int a_p = 0;    // (i) % 3   : produce A buffer
    int a_c = 1;    // (i-2) % 3 : consume A buffer
    #pragma unroll 1
    for (int i = 0; i <= 17; i++) {
        // ---- stream 1: produce block i (FFMA2 S + exp + A bf16 + psums) ----
        if (i < 16) {
            const int wb = i << 5;
            const int half = i & 1;
            u64 sacc[8][2];
            #pragma unroll
            for (int k = 0; k < 8; k++) { sacc[k][0] = 0ull; sacc[k][1] = 0ull; }

            #pragma unroll 8
            for (int h = 0; h < H_; h++) {
                ulonglong2 kk = *(const ulonglong2*)&sm[SK_OFF + h * W_ + v4];
                const float* qr = &sm[SQ_OFF + h * W_ + wb + (rgrpS << 3)];
                float4 qa = *(const float4*)qr;
                float4 qb = *(const float4*)(qr + 4);
                u64 d;
                d = dup2(qa.x); fma2(sacc[0][0], kk.x, d); fma2(sacc[0][1], kk.y, d);
                d = dup2(qa.y); fma2(sacc[1][0], kk.x, d); fma2(sacc[1][1], kk.y, d);
                d = dup2(qa.z); fma2(sacc[2][0], kk.x, d); fma2(sacc[2][1], kk.y, d);
                d = dup2(qa.w); fma2(sacc[3][0], kk.x, d); fma2(sacc[3][1], kk.y, d);
                d = dup2(qb.x); fma2(sacc[4][0], kk.x, d); fma2(sacc[4][1], kk.y, d);
                d = dup2(qb.y); fma2(sacc[5][0], kk.x, d); fma2(sacc[5][1], kk.y, d);
                d = dup2(qb.z); fma2(sacc[6][0], kk.x, d); fma2(sacc[6][1], kk.y, d);
                d = dup2(qb.w); fma2(sacc[7][0], kk.x, d); fma2(sacc[7][1], kk.y, d);
            }

            char* aB = smb + SCR_BYTE + a_p * 32768;
            float ps[8];
            #pragma unroll
            for (int k = 0; k < 8; k++) {
                float e0, e1, e2, e3;
                upk(sacc[k][0], e0, e1); upk(sacc[k][1], e2, e3);
                e0 = __expf(e0); e1 = __expf(e1); e2 = __expf(e2); e3 = __expf(e3);
                ps[k] = (e0 + e1) + (e2 + e3);
                u32 p0 = bfpair(e0, e1), p1 = bfpair(e2, e3);
                const int r = rgrpS * 8 + k;
                u32 bo = ((u32)(v4 * 2)) ^ ((u32)(k << 4));   // swizzle within 1024B row
                *(uint2*)(aB + r * 1024 + bo) = make_uint2(p0, p1);
            }
            #pragma unroll
            for (int k = 0; k < 8; k++)
                #pragma unroll
                for (int o = 16; o; o >>= 1) ps[k] += __shfl_xor_sync(0xffffffffu, ps[k], o);
            if (lane == 0) {
                #pragma unroll
                for (int k = 0; k < 8; k++)
                    sm[SSUM + half * 128 + (rgrpS * 8 + k) * 4 + wslot] = ps[k];
            }
        }

        // ---- stream 2: Vn build for block i-1 ----
        if (i >= 1 && i <= 16) {
            const int j = i - 1;
            const int jb = j & 1;
            const int wb = j << 5;
            const int h2 = tid >> 5, r = lane;
            float4 p4 = *(const float4*)&sm[SSUM + jb * 128 + r * 4];
            float rinv = __fdividef(1.0f, (p4.x + p4.y) + (p4.z + p4.w));
            float vn = sm[SV_OFF + h2 * W_ + wb + r] * rinv;
            *(unsigned short*)(smb + SVN_BYTE + jb * 1280 + h2 * 80 + r * 2)
                = (unsigned short)(bfpair(vn, 0.0f) & 0xFFFFu);
        }

        // ---- stream 3: consume block i-2 (8 bf16 HMMA / warp) ----
        if (i >= 2) {
            const int j = i - 2;
            const u32 ab = smem0 + SCR_BYTE + (u32)(a_c * 32768);
            const u32 bb = smem0 + SVN_BYTE + (u32)((j & 1) * 1280);
            u32 bfr[2][2][2];
            #pragma unroll
            for (int ni = 0; ni < 2; ni++)
                #pragma unroll
                for (int ks = 0; ks < 2; ks++) {
                    u32 addr = bb + (u32)((ni * 8 + (lane & 7)) * 80 + ks * 32 + ((lane >> 3) & 1) * 16);
                    asm volatile("ldmatrix.sync.aligned.m8n8.x2.shared.b16 {%0,%1}, [%2];"
                        : "=r"(bfr[ni][ks][0]), "=r"(bfr[ni][ks][1]) : "r"(addr));
                }
            #pragma unroll
            for (int mi = 0; mi < 2; mi++) {
                u32 af[2][4];
                #pragma unroll
                for (int ks = 0; ks < 2; ks++) {
                    const int r  = ks * 16 + a_roff + alr;
                    const int vb = (warp << 5) + (mi << 4) + a_voff;
                    u32 addr = ab + (u32)(r * 1024 + (((u32)(vb * 2)) ^ ((u32)(alr << 4))));
                    asm volatile("ldmatrix.sync.aligned.m8n8.x4.trans.shared.b16 {%0,%1,%2,%3}, [%4];"
                        : "=r"(af[ks][0]), "=r"(af[ks][1]), "=r"(af[ks][2]), "=r"(af[ks][3])
                        : "r"(addr));
                }
                #pragma unroll
                for (int ni = 0; ni < 2; ni++)
                    #pragma unroll
                    for (int ks = 0; ks < 2; ks++)
                        asm volatile(
                            "mma.sync.aligned.m16n8k16.row.col.f32.bf16.bf16.f32 "
                            "{%0,%1,%2,%3},{%4,%5,%6,%7},{%8,%9},{%0,%1,%2,%3};"
                            : "+f"(acc[mi][ni][0]), "+f"(acc[mi][ni][1]),
                              "+f"(acc[mi][ni][2]), "+f"(acc[mi][ni][3])
                            : "r"(af[ks][0]), "r"(af[ks][1]), "r"(af[ks][2]), "r"(af[ks][3]),
                              "r"(bfr[ni][ks][0]), "r"(bfr[ni][ks][1]));
            }
        }

        __syncthreads();   // single barrier: publish A(i)/psums(i)/Vn(i-1); free A((i-1)%3) for reuse

        a_p = (a_p == 2) ? 0 : a_p + 1;
        a_c = (a_c == 2) ? 0 : a_c + 1;
    }

    // ---------------- Epilogue: out = D + PE (PE read back from gmem) ----------------
    {
        const int vb = (warp << 5) + (lane >> 2);
        const int hb2 = (lane & 3) << 1;
        #pragma unroll
        for (int mi = 0; mi < 2; mi++)
            #pragma unroll
            for (int ni = 0; ni < 2; ni++) {
                const int v = vb + (mi << 4);
                const int h = hb2 + (ni << 3);
                float p0 = og[h * W_ + v];
                float p1 = og[(h + 1) * W_ + v];
                float p2 = og[h * W_ + v + 8];
                float p3 = og[(h + 1) * W_ + v + 8];
                og[h * W_ + v]           = acc[mi][ni][0] + p0;
                og[(h + 1) * W_ + v]     = acc[mi][ni][1] + p1;
                og[h * W_ + v + 8]       = acc[mi][ni][2] + p2;
                og[(h + 1) * W_ + v + 8] = acc[mi][ni][3] + p3;
            }
    }
}

extern "C" void kernel_launch(void* const* d_in, const int* in_sizes, int n_in,
                              void* d_out, int out_size)
{
    cudaFuncSetAttribute(conv_attn_fused_kernel,
                         cudaFuncAttributeMaxDynamicSharedMemorySize, SMEM_BYTES);

    const float* x  = (const float*)d_in[0];
    const float* wq = (const float*)d_in[1];
    const float* gq = (const float*)d_in[2];
    const float* bq = (const float*)d_in[3];
    const float* mq = (const float*)d_in[4];
    const float* vq = (const float*)d_in[5];
    const float* wk = (const float*)d_in[6];
    const float* gk = (const float*)d_in[7];
    const float* bk = (const float*)d_in[8];
    const float* mk = (const float*)d_in[9];
    const float* vk = (const float*)d_in[10];
    const float* wv = (const float*)d_in[11];
    const float* gv = (const float*)d_in[12];
    const float* bv = (const float*)d_in[13];
    const float* mv = (const float*)d_in[14];
    const float* vv = (const float*)d_in[15];
    const float* wp = (const float*)d_in[16];
    const float* gp = (const float*)d_in[17];
    const float* bp = (const float*)d_in[18];
    const float* mp = (const float*)d_in[19];
    const float* vp = (const float*)d_in[20];

    conv_attn_fused_kernel<<<B_ * COUT, 512, SMEM_BYTES>>>(
        x,
        wq, gq, bq, mq, vq,
        wk, gk, bk, mk, vk,
        wv, gv, bv, mv, vv,
        wp, gp, bp, mp, vp,
        (float*)d_out);
}

// round 13
// speedup vs baseline: 2.0321x; 2.0321x over previous
#include <cuda_runtime.h>
#include <cstdint>

#define B_   16
#define CIN  32
#define COUT 64
#define H_   16
#define W_   512
#define LRELU_SLOPE 0.3f
#define BN_EPS 1e-5f

typedef unsigned long long u64;
typedef unsigned int u32;

__device__ __forceinline__ void fma2(u64 &d, u64 a, u64 b) {
    asm("fma.rn.f32x2 %0,%1,%2,%0;" : "+l"(d) : "l"(a), "l"(b));
}
__device__ __forceinline__ void upk(u64 v, float &lo, float &hi) {
    asm("mov.b64 {%0,%1},%2;" : "=f"(lo), "=f"(hi) : "l"(v));
}
__device__ __forceinline__ u64 pk2(float lo, float hi) {
    u64 r; asm("mov.b64 %0,{%1,%2};" : "=l"(r) : "f"(lo), "f"(hi)); return r;
}
// pack (lo,hi) floats -> bf16x2 (lo in low 16 bits)
__device__ __forceinline__ u32 bfpair(float lo, float hi) {
    u32 r; asm("cvt.rn.satfinite.bf16x2.f32 %0, %1, %2;" : "=r"(r) : "f"(hi), "f"(lo)); return r;
}
// pack (lo,hi) floats -> f16x2 (lo in low 16 bits)
__device__ __forceinline__ u32 f16pair(float lo, float hi) {
    u32 r; asm("cvt.rn.f16x2.f32 %0, %1, %2;" : "=r"(r) : "f"(hi), "f"(lo)); return r;
}
__device__ __forceinline__ unsigned short f16one(float v) {
    unsigned short r;
    asm("{.reg .b16 t; cvt.rn.f16.f32 t, %1; mov.b16 %0, t;}" : "=h"(r) : "f"(v));
    return r;
}
__device__ __forceinline__ u32 smem_u32_of(const void* p) {
    u32 a; asm("{ .reg .u64 t; cvta.to.shared.u64 t, %1; cvt.u32.u64 %0, t; }" : "=r"(a) : "l"(p));
    return a;
}

// ---- SMEM layout (float offsets) ----
#define SQ_OFF    0                    // Q  16x512 fp32
#define SK16_OFF  8192                 // K  fp16 swizzled [16h][1024B rows]
#define SV_OFF    12288                // V  16x512 fp32
#define SPE_OFF   20480                // PE 16x512 fp32
#define SCR_OFF   28672                // union: conv staging 32x520 (16640) | A bf16 2x(32x1024B swz)
#define SQT_OFF   45312                // Qt fp16 2 x (32 rows x 48B)
#define SVN_OFF   46080                // Vn bf16 2 x (16 rows x 80B)
#define SSUM      46720                // 2 x [32 w-rows][20] fp32 warp-partials
#define SWOFF     48000                // weights [4t][32ci][12] dup'd
#define SBIAS     49536
#define SMEM_FLOATS 49540
#define SMEM_BYTES  (SMEM_FLOATS * 4)  // 198160 B

#define SK16_BYTE 32768
#define SCR_BYTE  114688               // 1024-aligned (A swizzle rows)
#define SQT_BYTE  181248
#define SVN_BYTE  184320

#define XROW 520

__global__ __launch_bounds__(512, 1)
void conv_attn_fused_kernel(
    const float* __restrict__ x,
    const float* __restrict__ wq, const float* __restrict__ gq, const float* __restrict__ bq, const float* __restrict__ mq, const float* __restrict__ vq,
    const float* __restrict__ wk, const float* __restrict__ gk, const float* __restrict__ bk, const float* __restrict__ mk, const float* __restrict__ vk,
    const float* __restrict__ wv, const float* __restrict__ gv, const float* __restrict__ bv, const float* __restrict__ mv, const float* __restrict__ vv,
    const float* __restrict__ wp, const float* __restrict__ gp, const float* __restrict__ bp, const float* __restrict__ mp, const float* __restrict__ vp,
    float* __restrict__ out)
{
    extern __shared__ float sm[];
    char* smb = (char*)sm;
    const int bid = blockIdx.x;
    const int b   = bid >> 6;
    const int c   = bid & 63;
    const int tid = threadIdx.x;
    const int warp = tid >> 5, lane = tid & 31;
    const u32 smem0 = smem_u32_of(sm);

    // ---------------- BN-folded weights, duplicated taps ----------------
    if (tid < 160) {
        const int ci = tid / 5, kk = tid - ci * 5;
        const int src = c * 160 + ci * 5 + kk;
        const int dst = ci * 12 + 2 * kk;
        float s, a;
        s = gq[c] * rsqrtf(vq[c] + BN_EPS); a = wq[src] * s;
        sm[SWOFF + 0*384 + dst] = a; sm[SWOFF + 0*384 + dst + 1] = a;
        s = gk[c] * rsqrtf(vk[c] + BN_EPS); a = wk[src] * s;
        sm[SWOFF + 1*384 + dst] = a; sm[SWOFF + 1*384 + dst + 1] = a;
        s = gv[c] * rsqrtf(vv[c] + BN_EPS); a = wv[src] * s;
        sm[SWOFF + 2*384 + dst] = a; sm[SWOFF + 2*384 + dst + 1] = a;
        s = gp[c] * rsqrtf(vp[c] + BN_EPS); a = wp[src] * s;
        sm[SWOFF + 3*384 + dst] = a; sm[SWOFF + 3*384 + dst + 1] = a;
    }
    if (tid == 0) {
        float s;
        s = gq[c] * rsqrtf(vq[c] + BN_EPS); sm[SBIAS + 0] = bq[c] - mq[c] * s;
        s = gk[c] * rsqrtf(vk[c] + BN_EPS); sm[SBIAS + 1] = bk[c] - mk[c] * s;
        s = gv[c] * rsqrtf(vv[c] + BN_EPS); sm[SBIAS + 2] = bv[c] - mv[c] * s;
        s = gp[c] * rsqrtf(vp[c] + BN_EPS); sm[SBIAS + 3] = bp[c] - mp[c] * s;
    }
    if (tid < 128) {   // zero staging halos {2,3,516,517} per row
        int row = tid >> 2, q4 = tid & 3;
        int off = (q4 < 2) ? (2 + q4) : (514 + q4);
        sm[SCR_OFF + row * XROW + off] = 0.0f;
    }

    // ---------------- Conv(1x5)+BN+LeakyReLU : 8h x 8w tiles, 2 passes ----------------
    const int hgrp = tid >> 6;
    const int w0c  = (tid & 63) << 3;
    const float* xb = x + (size_t)b * CIN * H_ * W_;

    for (int hb = 0; hb < 2; hb++) {
        u64 acc2[4][4];
        #pragma unroll
        for (int t = 0; t < 4; t++)
            #pragma unroll
            for (int j = 0; j < 4; j++) acc2[t][j] = 0ull;

        for (int cib = 0; cib < 8; cib++) {
            float4 stg[8];
            #pragma unroll
            for (int it = 0; it < 8; it++) {
                int i  = tid + (it << 9);
                int ci = i >> 10, hh = (i >> 7) & 7, w4 = (i & 127) << 2;
                stg[it] = *(const float4*)&xb[(((size_t)(cib*4 + ci)) * H_ + (hb*8 + hh)) * W_ + w4];
            }
            __syncthreads();
            #pragma unroll
            for (int it = 0; it < 8; it++) {
                int i  = tid + (it << 9);
                int ci = i >> 10, hh = (i >> 7) & 7, w4 = (i & 127) << 2;
                *(float4*)&sm[SCR_OFF + (ci*8 + hh) * XROW + 4 + w4] = stg[it];
            }
            __syncthreads();

            #pragma unroll
            for (int ci4 = 0; ci4 < 4; ci4++) {
                const float* xr = &sm[SCR_OFF + (ci4*8 + hgrp) * XROW + w0c];
                float4 f0 = *(const float4*)(xr);
                float4 f1 = *(const float4*)(xr + 4);
                float4 f2 = *(const float4*)(xr + 8);
                float4 f3 = *(const float4*)(xr + 12);
                float xm[16] = {f0.x,f0.y,f0.z,f0.w, f1.x,f1.y,f1.z,f1.w,
                                f2.x,f2.y,f2.z,f2.w, f3.x,f3.y,f3.z,f3.w};
                u64 P[11];
                #pragma unroll
                for (int n = 0; n < 11; n++) P[n] = pk2(xm[n+2], xm[n+3]);
                const int cig = cib*4 + ci4;
                #pragma unroll
                for (int t = 0; t < 4; t++) {
                    const float* wr = &sm[SWOFF + t*384 + cig*12];
                    ulonglong2 wa = *(const ulonglong2*)wr;
                    ulonglong2 wb2 = *(const ulonglong2*)(wr + 4);
                    u64 wc = *(const u64*)(wr + 8);
                    u64 w5[5] = { wa.x, wa.y, wb2.x, wb2.y, wc };
                    #pragma unroll
                    for (int kk2 = 0; kk2 < 5; kk2++)
                        #pragma unroll
                        for (int jp = 0; jp < 4; jp++)
                            fma2(acc2[t][jp], P[2*jp + kk2], w5[kk2]);
                }
            }
        }
        const int h = hb*8 + hgrp;
        #pragma unroll
        for (int t = 0; t < 4; t++) {
            float bias = sm[SBIAS + t];
            float y[8];
            #pragma unroll
            for (int jp = 0; jp < 4; jp++) {
                float lo, hi; upk(acc2[t][jp], lo, hi);
                y[2*jp]   = lo + bias;
                y[2*jp+1] = hi + bias;
            }
            #pragma unroll
            for (int j = 0; j < 8; j++) y[j] = (y[j] >= 0.f) ? y[j] : LRELU_SLOPE * y[j];
            if (t == 1) {
                // K -> fp16, swizzled rows (1024B, XOR (h&7)<<4)
                u32 bo = ((u32)((tid & 63) << 4)) ^ ((u32)((h & 7) << 4));
                *(uint4*)(smb + SK16_BYTE + h * 1024 + bo) =
                    make_uint4(f16pair(y[0], y[1]), f16pair(y[2], y[3]),
                               f16pair(y[4], y[5]), f16pair(y[6], y[7]));
            } else {
                float* d = (t == 0) ? (sm + SQ_OFF + h * W_ + w0c)
                         : (t == 2) ? (sm + SV_OFF + h * W_ + w0c)
                                    : (sm + SPE_OFF + h * W_ + w0c);
                *(float4*)(d)     = make_float4(y[0], y[1], y[2], y[3]);
                *(float4*)(d + 4) = make_float4(y[4], y[5], y[6], y[7]);
            }
        }
    }
    __syncthreads();   // Q/K16/V/PE ready; staging area becomes A double-buffer

    // ---------------- Attention: fp16 HMMA S -> exp -> A bf16 -> bf16 HMMA VxA ----------
    const int g  = lane >> 2, tg = lane & 3;
    const int agrp = lane >> 3, alr = lane & 7;
    const int a_voff = (agrp & 1) << 3;
    const int a_roff = (agrp >> 1) << 3;

    float acc[2][2][4];                   // consume D[v][h] fragments
    #pragma unroll
    for (int mi = 0; mi < 2; mi++)
        #pragma unroll
        for (int ni = 0; ni < 2; ni++)
            #pragma unroll
            for (int q = 0; q < 4; q++) acc[mi][ni][q] = 0.0f;

    // pre-stage Qt(0): Qt[w][h] fp16, 48B rows
    {
        int h = tid & 15, w = tid >> 4;
        *(unsigned short*)(smb + SQT_BYTE + w * 48 + h * 2)
            = f16one(sm[SQ_OFF + h * W_ + w]);
    }
    __syncthreads();

    #pragma unroll 1
    for (int i = 0; i <= 16; i++) {
        const int half = i & 1;
        if (i < 16) {
            // ---- produce block i : 8x m16n8k16 f16 MMA, exp, A bf16 store, psums ----
            const u32 qtb = smem0 + SQT_BYTE + (u32)(half * 1536);
            const u32 kb  = smem0 + SK16_BYTE;
            char* aB = smb + SCR_BYTE + half * 32768;

            u32 qa[2][4];
            #pragma unroll
            for (int mt = 0; mt < 2; mt++) {
                u32 addr = qtb + (u32)((mt * 16 + (lane & 15)) * 48 + ((lane >> 4) << 4));
                asm volatile("ldmatrix.sync.aligned.m8n8.x4.shared.b16 {%0,%1,%2,%3}, [%4];"
                    : "=r"(qa[mt][0]), "=r"(qa[mt][1]), "=r"(qa[mt][2]), "=r"(qa[mt][3])
                    : "r"(addr));
            }
            u32 kf[4][2];
            #pragma unroll
            for (int nt = 0; nt < 4; nt++) {
                int h16 = lane & 15;
                u32 v0b = (u32)(((warp << 5) + nt * 8) << 1);
                u32 addr = kb + (u32)(h16 * 1024) + (v0b ^ ((u32)((h16 & 7) << 4)));
                asm volatile("ldmatrix.sync.aligned.m8n8.x2.trans.shared.b16 {%0,%1}, [%2];"
                    : "=r"(kf[nt][0]), "=r"(kf[nt][1]) : "r"(addr));
            }

            float ps[2][2] = {{0.f, 0.f}, {0.f, 0.f}};
            #pragma unroll
            for (int mt = 0; mt < 2; mt++)
                #pragma unroll
                for (int nt = 0; nt < 4; nt++) {
                    float cf[4] = {0.f, 0.f, 0.f, 0.f};
                    asm volatile(
                        "mma.sync.aligned.m16n8k16.row.col.f32.f16.f16.f32 "
                        "{%0,%1,%2,%3},{%4,%5,%6,%7},{%8,%9},{%0,%1,%2,%3};"
                        : "+f"(cf[0]), "+f"(cf[1]), "+f"(cf[2]), "+f"(cf[3])
                        : "r"(qa[mt][0]), "r"(qa[mt][1]), "r"(qa[mt][2]), "r"(qa[mt][3]),
                          "r"(kf[nt][0]), "r"(kf[nt][1]));
                    float e0 = __expf(cf[0]), e1 = __expf(cf[1]);
                    float e2 = __expf(cf[2]), e3 = __expf(cf[3]);
                    ps[mt][0] += e0 + e1;
                    ps[mt][1] += e2 + e3;
                    const int wlo = mt * 16 + g, whi = wlo + 8;
                    u32 vqb = (u32)((((warp << 5) + nt * 8 + (tg << 1))) << 1);
                    u32 swz = (u32)(g << 4);
                    *(u32*)(aB + wlo * 1024 + (vqb ^ swz)) = bfpair(e0, e1);
                    *(u32*)(aB + whi * 1024 + (vqb ^ swz)) = bfpair(e2, e3);
                }
            #pragma unroll
            for (int mt = 0; mt < 2; mt++)
                #pragma unroll
                for (int q = 0; q < 2; q++) {
                    ps[mt][q] += __shfl_xor_sync(0xffffffffu, ps[mt][q], 1);
                    ps[mt][q] += __shfl_xor_sync(0xffffffffu, ps[mt][q], 2);
                }
            if (tg == 0) {
                #pragma unroll
                for (int mt = 0; mt < 2; mt++) {
                    sm[SSUM + half * 640 + (mt * 16 + g) * 20 + warp]     = ps[mt][0];
                    sm[SSUM + half * 640 + (mt * 16 + g + 8) * 20 + warp] = ps[mt][1];
                }
            }
        }
        __syncthreads();   // b0: A(i) + psums(i) visible

        if (i < 16) {
            // ---- Vn[h][w] = V[h][wb+w] * rinv(w), bf16, 80B row stride ----
            const int wb = i << 5;
            const int h2 = tid >> 5, r = lane;
            const float* pp = &sm[SSUM + half * 640 + r * 20];
            float4 s0 = *(const float4*)(pp);
            float4 s1 = *(const float4*)(pp + 4);
            float4 s2 = *(const float4*)(pp + 8);
            float4 s3 = *(const float4*)(pp + 12);
            float ssum = ((s0.x + s0.y) + (s0.z + s0.w)) + ((s1.x + s1.y) + (s1.z + s1.w))
                       + ((s2.x + s2.y) + (s2.z + s2.w)) + ((s3.x + s3.y) + (s3.z + s3.w));
            float vn = sm[SV_OFF + h2 * W_ + wb + r] * __fdividef(1.0f, ssum);
            *(unsigned short*)(smb + SVN_BYTE + half * 1280 + h2 * 80 + r * 2)
                = (unsigned short)(bfpair(vn, 0.0f) & 0xFFFFu);
        }
        if (i < 15) {
            // ---- stage Qt(i+1) into buffer (i+1)&1 ----
            int h = tid & 15, w = tid >> 4;
            *(unsigned short*)(smb + SQT_BYTE + ((i + 1) & 1) * 1536 + w * 48 + h * 2)
                = f16one(sm[SQ_OFF + h * W_ + ((i + 1) << 5) + w]);
        }

        if (i > 0) {
            // ---- consume block i-1 : D[v][h] += A'[v][w] * Vn[w][h] (R10 verbatim) ----
            const int cbk = (i - 1) & 1;
            const u32 ab = smem0 + SCR_BYTE + (u32)(cbk * 32768);
            const u32 bb = smem0 + SVN_BYTE + (u32)(cbk * 1280);
            u32 bfr[2][2][2];
            #pragma unroll
            for (int ni = 0; ni < 2; ni++)
                #pragma unroll
                for (int ks = 0; ks < 2; ks++) {
                    u32 addr = bb + (u32)((ni * 8 + (lane & 7)) * 80 + ks * 32 + ((lane >> 3) & 1) * 16);
                    asm volatile("ldmatrix.sync.aligned.m8n8.x2.shared.b16 {%0,%1}, [%2];"
                        : "=r"(bfr[ni][ks][0]), "=r"(bfr[ni][ks][1]) : "r"(addr));
                }
            #pragma unroll
            for (int mi = 0; mi < 2; mi++) {
                u32 af[2][4];
                #pragma unroll
                for (int ks = 0; ks < 2; ks++) {
                    const int r  = ks * 16 + a_roff + alr;
                    const int vb = (warp << 5) + (mi << 4) + a_voff;
                    u32 addr = ab + (u32)(r * 1024 + (((u32)(vb * 2)) ^ ((u32)(alr << 4))));
                    asm volatile("ldmatrix.sync.aligned.m8n8.x4.trans.shared.b16 {%0,%1,%2,%3}, [%4];"
                        : "=r"(af[ks][0]), "=r"(af[ks][1]), "=r"(af[ks][2]), "=r"(af[ks][3])
                        : "r"(addr));
                }
                #pragma unroll
                for (int ni = 0; ni < 2; ni++)
                    #pragma unroll
                    for (int ks = 0; ks < 2; ks++)
                        asm volatile(
                            "mma.sync.aligned.m16n8k16.row.col.f32.bf16.bf16.f32 "
                            "{%0,%1,%2,%3},{%4,%5,%6,%7},{%8,%9},{%0,%1,%2,%3};"
                            : "+f"(acc[mi][ni][0]), "+f"(acc[mi][ni][1]),
                              "+f"(acc[mi][ni][2]), "+f"(acc[mi][ni][3])
                            : "r"(af[ks][0]), "r"(af[ks][1]), "r"(af[ks][2]), "r"(af[ks][3]),
                              "r"(bfr[ni][ks][0]), "r"(bfr[ni][ks][1]));
            }
        }
        __syncthreads();   // b1: Vn(i)+Qt(i+1) published; A(i-1)/Vn(i-1) reads done
    }

    // ---------------- Epilogue: D + PE -> gmem straight from fragments ----------------
    float* og = out + (size_t)bid * (H_ * W_);
    {
        const int vb = (warp << 5) + (lane >> 2);
        const int hb2 = (lane & 3) << 1;
        #pragma unroll
        for (int mi = 0; mi < 2; mi++)
            #pragma unroll
            for (int ni = 0; ni < 2; ni++) {
                const int v = vb + (mi << 4);
                const int h = hb2 + (ni << 3);
                og[h * W_ + v]           = acc[mi][ni][0] + sm[SPE_OFF + h * W_ + v];
                og[(h + 1) * W_ + v]     = acc[mi][ni][1] + sm[SPE_OFF + (h + 1) * W_ + v];
                og[h * W_ + v + 8]       = acc[mi][ni][2] + sm[SPE_OFF + h * W_ + v + 8];
                og[(h + 1) * W_ + v + 8] = acc[mi][ni][3] + sm[SPE_OFF + (h + 1) * W_ + v + 8];
            }
    }
}

extern "C" void kernel_launch(void* const* d_in, const int* in_sizes, int n_in,
                              void* d_out, int out_size)
{
    cudaFuncSetAttribute(conv_attn_fused_kernel,
                         cudaFuncAttributeMaxDynamicSharedMemorySize, SMEM_BYTES);

    const float* x  = (const float*)d_in[0];
    const float* wq = (const float*)d_in[1];
    const float* gq = (const float*)d_in[2];
    const float* bq = (const float*)d_in[3];
    const float* mq = (const float*)d_in[4];
    const float* vq = (const float*)d_in[5];
    const float* wk = (const float*)d_in[6];
    const float* gk = (const float*)d_in[7];
    const float* bk = (const float*)d_in[8];
    const float* mk = (const float*)d_in[9];
    const float* vk = (const float*)d_in[10];
    const float* wv = (const float*)d_in[11];
    const float* gv = (const float*)d_in[12];
    const float* bv = (const float*)d_in[13];
    const float* mv = (const float*)d_in[14];
    const float* vv = (const float*)d_in[15];
    const float* wp = (const float*)d_in[16];
    const float* gp = (const float*)d_in[17];
    const float* bp = (const float*)d_in[18];
    const float* mp = (const float*)d_in[19];
    const float* vp = (const float*)d_in[20];

    conv_attn_fused_kernel<<<B_ * COUT, 512, SMEM_BYTES>>>(
        x,
        wq, gq, bq, mq, vq,
        wk, gk, bk, mk, vk,
        wv, gv, bv, mv, vv,
        wp, gp, bp, mp, vp,
        (float*)d_out);
}

// round 14
// speedup vs baseline: 2.6922x; 1.3248x over previous
#include <cuda_runtime.h>
#include <cstdint>

#define B_   16
#define CIN  32
#define COUT 64
#define H_   16
#define W_   512
#define LRELU_SLOPE 0.3f
#define BN_EPS 1e-5f

typedef unsigned long long u64;
typedef unsigned int u32;
typedef unsigned short u16;

// pack (lo,hi) floats -> bf16x2 (lo in low 16 bits)
__device__ __forceinline__ u32 bfpair(float lo, float hi) {
    u32 r; asm("cvt.rn.satfinite.bf16x2.f32 %0, %1, %2;" : "=r"(r) : "f"(hi), "f"(lo)); return r;
}
// pack (lo,hi) floats -> f16x2 (lo in low 16 bits)
__device__ __forceinline__ u32 f16pair(float lo, float hi) {
    u32 r; asm("cvt.rn.f16x2.f32 %0, %1, %2;" : "=r"(r) : "f"(hi), "f"(lo)); return r;
}
__device__ __forceinline__ u16 f16one(float v) {
    u16 r;
    asm("{.reg .b16 t; cvt.rn.f16.f32 t, %1; mov.b16 %0, t;}" : "=h"(r) : "f"(v));
    return r;
}
__device__ __forceinline__ float f16tof32(u16 v) {
    float r;
    asm("{.reg .b16 t; mov.b16 t, %1; cvt.f32.f16 %0, t;}" : "=f"(r) : "h"(v));
    return r;
}
__device__ __forceinline__ u32 smem_u32_of(const void* p) {
    u32 a; asm("{ .reg .u64 t; cvta.to.shared.u64 t, %1; cvt.u32.u64 %0, t; }" : "=r"(a) : "l"(p));
    return a;
}

// ---- SMEM layout ----
// floats:
#define SPE_OFF   16384               // PE 16x512 fp32
#define SSUM      42240               // 2 x [32 w-rows][20] fp32 warp-partials
#define SBIAS     43520               // 8 biases (4 used + 0-pad)
#define SMEM_FLOATS 43528
#define SMEM_BYTES  (SMEM_FLOATS * 4) // 174112 B
// bytes:
#define QT_BYTE   0                   // Qt fp16 [512 w][48B rows (16h + pad)]
#define K16_BYTE  24576               // K fp16 [16h][1024B swizzled rows]
#define VT_BYTE   40960               // Vt fp16 [512 w][48B rows]
#define SCR_BYTE  98304               // union: conv XT fp16 [520 rows x 80B] | A bf16 2x(32x1024B swz)
#define W16_BYTE  163840              // W fp16 [5 tap][32ci rows x 16B (8t)]
#define VN_BYTE   166400              // Vn bf16 2 x (16 rows x 80B)

__global__ __launch_bounds__(512, 1)
void conv_attn_fused_kernel(
    const float* __restrict__ x,
    const float* __restrict__ wq, const float* __restrict__ gq, const float* __restrict__ bq, const float* __restrict__ mq, const float* __restrict__ vq,
    const float* __restrict__ wk, const float* __restrict__ gk, const float* __restrict__ bk, const float* __restrict__ mk, const float* __restrict__ vk,
    const float* __restrict__ wv, const float* __restrict__ gv, const float* __restrict__ bv, const float* __restrict__ mv, const float* __restrict__ vv,
    const float* __restrict__ wp, const float* __restrict__ gp, const float* __restrict__ bp, const float* __restrict__ mp, const float* __restrict__ vp,
    float* __restrict__ out)
{
    extern __shared__ float sm[];
    char* smb = (char*)sm;
    const int bid = blockIdx.x;
    const int b   = bid >> 6;
    const int c   = bid & 63;
    const int tid = threadIdx.x;
    const int warp = tid >> 5, lane = tid & 31;
    const u32 smem0 = smem_u32_of(sm);

    // ---------------- BN-folded weights -> fp16 [tap][ci][8t], biases ----------------
    if (tid < 160) {
        const int ci = tid / 5, kk = tid - ci * 5;
        const int src = c * 160 + ci * 5 + kk;
        float s0 = gq[c] * rsqrtf(vq[c] + BN_EPS);
        float s1 = gk[c] * rsqrtf(vk[c] + BN_EPS);
        float s2 = gv[c] * rsqrtf(vv[c] + BN_EPS);
        float s3 = gp[c] * rsqrtf(vp[c] + BN_EPS);
        char* wd = smb + W16_BYTE + kk * 512 + ci * 16;
        *(u32*)(wd)      = f16pair(wq[src] * s0, wk[src] * s1);
        *(u32*)(wd + 4)  = f16pair(wv[src] * s2, wp[src] * s3);
        *(u32*)(wd + 8)  = 0u;
        *(u32*)(wd + 12) = 0u;
    }
    if (tid == 0) {
        float s;
        s = gq[c] * rsqrtf(vq[c] + BN_EPS); sm[SBIAS + 0] = bq[c] - mq[c] * s;
        s = gk[c] * rsqrtf(vk[c] + BN_EPS); sm[SBIAS + 1] = bk[c] - mk[c] * s;
        s = gv[c] * rsqrtf(vv[c] + BN_EPS); sm[SBIAS + 2] = bv[c] - mv[c] * s;
        s = gp[c] * rsqrtf(vp[c] + BN_EPS); sm[SBIAS + 3] = bp[c] - mp[c] * s;
        sm[SBIAS + 4] = 0.f; sm[SBIAS + 5] = 0.f; sm[SBIAS + 6] = 0.f; sm[SBIAS + 7] = 0.f;
    }
    // zero XT halo rows {0,1,514,515} (buffer row = w+2; main stores touch rows 2..513 only)
    if (tid < 80) {
        int ri = tid / 20, col = tid % 20;
        int row = (ri < 2) ? ri : (ri + 512);
        *(u32*)(smb + SCR_BYTE + row * 80 + col * 4) = 0u;
    }

    // ---------------- Conv(1x5)+BN+LeakyReLU on tensor cores ----------------
    // Per tap k: Y[w][t] += XT[w+k-2][ci] x Wk[ci][t]   (M=16w, N=8t(4 used), K=16ci x2)
    const float* xb = x + (size_t)b * CIN * H_ * W_;
    const int g  = lane >> 2, tg = lane & 3;

    // prefetch h = 0 (thread covers 4 w-groups x 4 ci-chunks, f16x2 each)
    u32 pf[16];
    {
        const int rr = lane >> 2, wq2 = (lane & 3) << 1;
        #pragma unroll
        for (int p = 0; p < 4; p++) {
            int w0s = (warp * 4 + p) << 3;
            #pragma unroll
            for (int cq = 0; cq < 4; cq++) {
                const float* px = xb + (size_t)(cq * 8 + rr) * (H_ * W_) + 0 * W_ + w0s + wq2;
                float2 v = *(const float2*)px;
                pf[p * 4 + cq] = f16pair(v.x, v.y);
            }
        }
    }
    __syncthreads();   // weights + halos visible

    // persistent weight B-frags: [tap][kstep][2]
    u32 wf[5][2][2];
    #pragma unroll
    for (int k = 0; k < 5; k++)
        #pragma unroll
        for (int ks = 0; ks < 2; ks++) {
            u32 addr = smem0 + W16_BYTE + (u32)(k * 512 + ((ks << 4) + (lane & 15)) * 16);
            asm volatile("ldmatrix.sync.aligned.m8n8.x2.trans.shared.b16 {%0,%1}, [%2];"
                : "=r"(wf[k][ks][0]), "=r"(wf[k][ks][1]) : "r"(addr));
        }

    #pragma unroll 1
    for (int h = 0; h < H_; h++) {
        // store staged rows: stmatrix.x4.trans -> XT[w+2][ci] (stride 80B, conflict-free)
        #pragma unroll
        for (int p = 0; p < 4; p++) {
            int w0s = (warp * 4 + p) << 3;
            u32 addr = smem0 + SCR_BYTE + (u32)((w0s + 2 + (lane & 7)) * 80 + ((lane >> 3) << 4));
            asm volatile("stmatrix.sync.aligned.m8n8.x4.trans.shared.b16 [%0], {%1,%2,%3,%4};"
                :: "r"(addr), "r"(pf[p * 4 + 0]), "r"(pf[p * 4 + 1]),
                   "r"(pf[p * 4 + 2]), "r"(pf[p * 4 + 3]) : "memory");
        }
        __syncthreads();   // XT(h) ready

        // prefetch h+1
        if (h < 15) {
            const int rr = lane >> 2, wq2 = (lane & 3) << 1;
            #pragma unroll
            for (int p = 0; p < 4; p++) {
                int w0s = (warp * 4 + p) << 3;
                #pragma unroll
                for (int cq = 0; cq < 4; cq++) {
                    const float* px = xb + (size_t)(cq * 8 + rr) * (H_ * W_) + (h + 1) * W_ + w0s + wq2;
                    float2 v = *(const float2*)px;
                    pf[p * 4 + cq] = f16pair(v.x, v.y);
                }
            }
        }

        // compute: 2 M-tiles x 5 taps x 2 ksteps
        #pragma unroll
        for (int mt = 0; mt < 2; mt++) {
            const int w0 = warp * 32 + mt * 16;
            float c0 = 0.f, c1 = 0.f, c2 = 0.f, c3 = 0.f;
            #pragma unroll
            for (int tap = 0; tap < 5; tap++)
                #pragma unroll
                for (int ks = 0; ks < 2; ks++) {
                    u32 a0, a1, a2, a3;
                    u32 addr = smem0 + SCR_BYTE
                             + (u32)((w0 + tap + (lane & 15)) * 80 + ((lane >> 4) << 4) + (ks << 5));
                    asm volatile("ldmatrix.sync.aligned.m8n8.x4.shared.b16 {%0,%1,%2,%3}, [%4];"
                        : "=r"(a0), "=r"(a1), "=r"(a2), "=r"(a3) : "r"(addr));
                    asm volatile(
                        "mma.sync.aligned.m16n8k16.row.col.f32.f16.f16.f32 "
                        "{%0,%1,%2,%3},{%4,%5,%6,%7},{%8,%9},{%0,%1,%2,%3};"
                        : "+f"(c0), "+f"(c1), "+f"(c2), "+f"(c3)
                        : "r"(a0), "r"(a1), "r"(a2), "r"(a3),
                          "r"(wf[tap][ks][0]), "r"(wf[tap][ks][1]));
                }
            // epilogue: bias + lrelu, scatter per-tensor layouts
            if (tg < 2) {
                float blo = sm[SBIAS + 2 * tg], bhi = sm[SBIAS + 2 * tg + 1];
                float y00 = c0 + blo, y01 = c1 + bhi, y10 = c2 + blo, y11 = c3 + bhi;
                y00 = fmaxf(y00, LRELU_SLOPE * y00);
                y01 = fmaxf(y01, LRELU_SLOPE * y01);
                y10 = fmaxf(y10, LRELU_SLOPE * y10);
                y11 = fmaxf(y11, LRELU_SLOPE * y11);
                const int w = w0 + g;
                if (tg == 0) {
                    // t0 = Q -> Qt16[w][h] ; t1 = K -> K16[h][v] swizzled
                    *(u16*)(smb + QT_BYTE + w * 48 + h * 2)       = f16one(y00);
                    *(u16*)(smb + QT_BYTE + (w + 8) * 48 + h * 2) = f16one(y10);
                    *(u16*)(smb + K16_BYTE + h * 1024 + ((u32)(2 * w)       ^ ((u32)((h & 7) << 4)))) = f16one(y01);
                    *(u16*)(smb + K16_BYTE + h * 1024 + ((u32)(2 * (w + 8)) ^ ((u32)((h & 7) << 4)))) = f16one(y11);
                } else {
                    // t2 = V -> Vt16[w][h] ; t3 = PE -> smem fp32 [h][w]
                    *(u16*)(smb + VT_BYTE + w * 48 + h * 2)       = f16one(y00);
                    *(u16*)(smb + VT_BYTE + (w + 8) * 48 + h * 2) = f16one(y10);
                    sm[SPE_OFF + h * W_ + w]     = y01;
                    sm[SPE_OFF + h * W_ + w + 8] = y11;
                }
            }
        }
        __syncthreads();   // compute(h) done; XT free for h+1
    }
    // Qt16/K16/Vt16/PE ready; SCR becomes A double-buffer

    // ---------------- Attention: fp16 HMMA S -> exp -> A bf16 -> bf16 HMMA VxA ----------
    const int agrp = lane >> 3, alr = lane & 7;
    const int a_voff = (agrp & 1) << 3;
    const int a_roff = (agrp >> 1) << 3;

    float acc[2][2][4];
    #pragma unroll
    for (int mi = 0; mi < 2; mi++)
        #pragma unroll
        for (int ni = 0; ni < 2; ni++)
            #pragma unroll
            for (int q = 0; q < 4; q++) acc[mi][ni][q] = 0.0f;

    #pragma unroll 1
    for (int i = 0; i <= 16; i++) {
        const int half = i & 1;
        if (i < 16) {
            // ---- produce block i : 8x m16n8k16 f16 MMA, exp, A bf16 store, psums ----
            char* aB = smb + SCR_BYTE + half * 32768;

            u32 qa[2][4];
            #pragma unroll
            for (int mt = 0; mt < 2; mt++) {
                u32 addr = smem0 + QT_BYTE
                         + (u32)(((i << 5) + mt * 16 + (lane & 15)) * 48 + ((lane >> 4) << 4));
                asm volatile("ldmatrix.sync.aligned.m8n8.x4.shared.b16 {%0,%1,%2,%3}, [%4];"
                    : "=r"(qa[mt][0]), "=r"(qa[mt][1]), "=r"(qa[mt][2]), "=r"(qa[mt][3])
                    : "r"(addr));
            }
            u32 kf[4][2];
            #pragma unroll
            for (int nt = 0; nt < 4; nt++) {
                int h16 = lane & 15;
                u32 v0b = (u32)(((warp << 5) + nt * 8) << 1);
                u32 addr = smem0 + K16_BYTE + (u32)(h16 * 1024) + (v0b ^ ((u32)((h16 & 7) << 4)));
                asm volatile("ldmatrix.sync.aligned.m8n8.x2.trans.shared.b16 {%0,%1}, [%2];"
                    : "=r"(kf[nt][0]), "=r"(kf[nt][1]) : "r"(addr));
            }

            float ps[2][2] = {{0.f, 0.f}, {0.f, 0.f}};
            #pragma unroll
            for (int mt = 0; mt < 2; mt++)
                #pragma unroll
                for (int nt = 0; nt < 4; nt++) {
                    float cf[4] = {0.f, 0.f, 0.f, 0.f};
                    asm volatile(
                        "mma.sync.aligned.m16n8k16.row.col.f32.f16.f16.f32 "
                        "{%0,%1,%2,%3},{%4,%5,%6,%7},{%8,%9},{%0,%1,%2,%3};"
                        : "+f"(cf[0]), "+f"(cf[1]), "+f"(cf[2]), "+f"(cf[3])
                        : "r"(qa[mt][0]), "r"(qa[mt][1]), "r"(qa[mt][2]), "r"(qa[mt][3]),
                          "r"(kf[nt][0]), "r"(kf[nt][1]));
                    float e0 = __expf(cf[0]), e1 = __expf(cf[1]);
                    float e2 = __expf(cf[2]), e3 = __expf(cf[3]);
                    ps[mt][0] += e0 + e1;
                    ps[mt][1] += e2 + e3;
                    const int wlo = mt * 16 + g, whi = wlo + 8;
                    u32 vqb = (u32)((((warp << 5) + nt * 8 + (tg << 1))) << 1);
                    u32 swz = (u32)(g << 4);
                    *(u32*)(aB + wlo * 1024 + (vqb ^ swz)) = bfpair(e0, e1);
                    *(u32*)(aB + whi * 1024 + (vqb ^ swz)) = bfpair(e2, e3);
                }
            #pragma unroll
            for (int mt = 0; mt < 2; mt++)
                #pragma unroll
                for (int q = 0; q < 2; q++) {
                    ps[mt][q] += __shfl_xor_sync(0xffffffffu, ps[mt][q], 1);
                    ps[mt][q] += __shfl_xor_sync(0xffffffffu, ps[mt][q], 2);
                }
            if (tg == 0) {
                #pragma unroll
                for (int mt = 0; mt < 2; mt++) {
                    sm[SSUM + half * 640 + (mt * 16 + g) * 20 + warp]     = ps[mt][0];
                    sm[SSUM + half * 640 + (mt * 16 + g + 8) * 20 + warp] = ps[mt][1];
                }
            }
        }
        __syncthreads();   // b0: A(i) + psums(i) visible

        if (i < 16) {
            // ---- Vn[h][w] = Vt16[wb+w][h] * rinv(w), bf16, 80B row stride ----
            const int wb = i << 5;
            const int h2 = tid >> 5, r = lane;
            const float* pp = &sm[SSUM + half * 640 + r * 20];
            float4 s0 = *(const float4*)(pp);
            float4 s1 = *(const float4*)(pp + 4);
            float4 s2 = *(const float4*)(pp + 8);
            float4 s3 = *(const float4*)(pp + 12);
            float ssum = ((s0.x + s0.y) + (s0.z + s0.w)) + ((s1.x + s1.y) + (s1.z + s1.w))
                       + ((s2.x + s2.y) + (s2.z + s2.w)) + ((s3.x + s3.y) + (s3.z + s3.w));
            u16 vraw = *(const u16*)(smb + VT_BYTE + (wb + r) * 48 + h2 * 2);
            float vn = f16tof32(vraw) * __fdividef(1.0f, ssum);
            *(u16*)(smb + VN_BYTE + half * 1280 + h2 * 80 + r * 2)
                = (u16)(bfpair(vn, 0.0f) & 0xFFFFu);
        }

        if (i > 0) {
            // ---- consume block i-1 : D[v][h] += A'[v][w] * Vn[w][h] ----
            const int cbk = (i - 1) & 1;
            const u32 ab = smem0 + SCR_BYTE + (u32)(cbk * 32768);
            const u32 bb = smem0 + VN_BYTE + (u32)(cbk * 1280);
            u32 bfr[2][2][2];
            #pragma unroll
            for (int ni = 0; ni < 2; ni++)
                #pragma unroll
                for (int ks = 0; ks < 2; ks++) {
                    u32 addr = bb + (u32)((ni * 8 + (lane & 7)) * 80 + ks * 32 + ((lane >> 3) & 1) * 16);
                    asm volatile("ldmatrix.sync.aligned.m8n8.x2.shared.b16 {%0,%1}, [%2];"
                        : "=r"(bfr[ni][ks][0]), "=r"(bfr[ni][ks][1]) : "r"(addr));
                }
            #pragma unroll
            for (int mi = 0; mi < 2; mi++) {
                u32 af[2][4];
                #pragma unroll
                for (int ks = 0; ks < 2; ks++) {
                    const int r  = ks * 16 + a_roff + alr;
                    const int vb = (warp << 5) + (mi << 4) + a_voff;
                    u32 addr = ab + (u32)(r * 1024 + (((u32)(vb * 2)) ^ ((u32)(alr << 4))));
                    asm volatile("ldmatrix.sync.aligned.m8n8.x4.trans.shared.b16 {%0,%1,%2,%3}, [%4];"
                        : "=r"(af[ks][0]), "=r"(af[ks][1]), "=r"(af[ks][2]), "=r"(af[ks][3])
                        : "r"(addr));
                }
                #pragma unroll
                for (int ni = 0; ni < 2; ni++)
                    #pragma unroll
                    for (int ks = 0; ks < 2; ks++)
                        asm volatile(
                            "mma.sync.aligned.m16n8k16.row.col.f32.bf16.bf16.f32 "
                            "{%0,%1,%2,%3},{%4,%5,%6,%7},{%8,%9},{%0,%1,%2,%3};"
                            : "+f"(acc[mi][ni][0]), "+f"(acc[mi][ni][1]),
                              "+f"(acc[mi][ni][2]), "+f"(acc[mi][ni][3])
                            : "r"(af[ks][0]), "r"(af[ks][1]), "r"(af[ks][2]), "r"(af[ks][3]),
                              "r"(bfr[ni][ks][0]), "r"(bfr[ni][ks][1]));
            }
        }
        __syncthreads();   // b1: Vn(i) published; A(i-1)/Vn(i-1) reads done
    }

    // ---------------- Epilogue: D + PE -> gmem straight from fragments ----------------
    float* og = out + (size_t)bid * (H_ * W_);
    {
        const int vb = (warp << 5) + (lane >> 2);
        const int hb2 = (lane & 3) << 1;
        #pragma unroll
        for (int mi = 0; mi < 2; mi++)
            #pragma unroll
            for (int ni = 0; ni < 2; ni++) {
                const int v = vb + (mi << 4);
                const int h = hb2 + (ni << 3);
                og[h * W_ + v]           = acc[mi][ni][0] + sm[SPE_OFF + h * W_ + v];
                og[(h + 1) * W_ + v]     = acc[mi][ni][1] + sm[SPE_OFF + (h + 1) * W_ + v];
                og[h * W_ + v + 8]       = acc[mi][ni][2] + sm[SPE_OFF + h * W_ + v + 8];
                og[(h + 1) * W_ + v + 8] = acc[mi][ni][3] + sm[SPE_OFF + (h + 1) * W_ + v + 8];
            }
    }
}

extern "C" void kernel_launch(void* const* d_in, const int* in_sizes, int n_in,
                              void* d_out, int out_size)
{
    cudaFuncSetAttribute(conv_attn_fused_kernel,
                         cudaFuncAttributeMaxDynamicSharedMemorySize, SMEM_BYTES);

    const float* x  = (const float*)d_in[0];
    const float* wq = (const float*)d_in[1];
    const float* gq = (const float*)d_in[2];
    const float* bq = (const float*)d_in[3];
    const float* mq = (const float*)d_in[4];
    const float* vq = (const float*)d_in[5];
    const float* wk = (const float*)d_in[6];
    const float* gk = (const float*)d_in[7];
    const float* bk = (const float*)d_in[8];
    const float* mk = (const float*)d_in[9];
    const float* vk = (const float*)d_in[10];
    const float* wv = (const float*)d_in[11];
    const float* gv = (const float*)d_in[12];
    const float* bv = (const float*)d_in[13];
    const float* mv = (const float*)d_in[14];
    const float* vv = (const float*)d_in[15];
    const float* wp = (const float*)d_in[16];
    const float* gp = (const float*)d_in[17];
    const float* bp = (const float*)d_in[18];
    const float* mp = (const float*)d_in[19];
    const float* vp = (const float*)d_in[20];

    conv_attn_fused_kernel<<<B_ * COUT, 512, SMEM_BYTES>>>(
        x,
        wq, gq, bq, mq, vq,
        wk, gk, bk, mk, vk,
        wv, gv, bv, mv, vv,
        wp, gp, bp, mp, vp,
        (float*)d_out);
}

// round 17
// speedup vs baseline: 2.8135x; 1.0451x over previous
#include <cuda_runtime.h>
#include <cstdint>

#define B_   16
#define CIN  32
#define COUT 64
#define H_   16
#define W_   512
#define LRELU_SLOPE 0.3f
#define BN_EPS 1e-5f

typedef unsigned long long u64;
typedef unsigned int u32;
typedef unsigned short u16;

__device__ __forceinline__ u32 bfpair(float lo, float hi) {
    u32 r; asm("cvt.rn.satfinite.bf16x2.f32 %0, %1, %2;" : "=r"(r) : "f"(hi), "f"(lo)); return r;
}
__device__ __forceinline__ u32 f16pair(float lo, float hi) {
    u32 r; asm("cvt.rn.f16x2.f32 %0, %1, %2;" : "=r"(r) : "f"(hi), "f"(lo)); return r;
}
__device__ __forceinline__ u16 f16one(float v) {
    u16 r;
    asm("{.reg .b16 t; cvt.rn.f16.f32 t, %1; mov.b16 %0, t;}" : "=h"(r) : "f"(v));
    return r;
}
__device__ __forceinline__ float f16tof32(u16 v) {
    float r;
    asm("{.reg .b16 t; mov.b16 t, %1; cvt.f32.f16 %0, t;}" : "=f"(r) : "h"(v));
    return r;
}
__device__ __forceinline__ u32 smem_u32_of(const void* p) {
    u32 a; asm("{ .reg .u64 t; cvta.to.shared.u64 t, %1; cvt.u32.u64 %0, t; }" : "=r"(a) : "l"(p));
    return a;
}

// ---- SMEM layout (bytes) — total 109,728 B => 2 CTAs/SM ----
#define QT_BYTE   0          // Qt fp16 [512 w][48B rows]
#define K16_BYTE  24576      // K fp16 [16h][1024B swizzled rows]
#define VT_BYTE   40960      // Vt fp16 [512 w][48B rows]
#define SCR_BYTE  65536      // union: conv XT fp16 [520 x 80B] (41600) | { A bf16 32x1024B + VN + SSUM }
#define A_BYTE    65536      // A bf16 single buffer 32768
#define VN_BYTE   98304      // Vn bf16 [16 x 80B] = 1280
#define SSUM_BYTE 99584      // [32 w][20] fp32 = 2560
#define W16_BYTE  107136     // W fp16 [5 tap][32ci x 16B] = 2560
#define SBIAS_B   109696     // 8 floats
#define SMEM_BYTES 109728

__global__ __launch_bounds__(512, 2)
void conv_attn_fused_kernel(
    const float* __restrict__ x,
    const float* __restrict__ wq, const float* __restrict__ gq, const float* __restrict__ bq, const float* __restrict__ mq, const float* __restrict__ vq,
    const float* __restrict__ wk, const float* __restrict__ gk, const float* __restrict__ bk, const float* __restrict__ mk, const float* __restrict__ vk,
    const float* __restrict__ wv, const float* __restrict__ gv, const float* __restrict__ bv, const float* __restrict__ mv, const float* __restrict__ vv,
    const float* __restrict__ wp, const float* __restrict__ gp, const float* __restrict__ bp, const float* __restrict__ mp, const float* __restrict__ vp,
    float* __restrict__ out)
{
    extern __shared__ float sm[];
    char* smb = (char*)sm;
    const int bid = blockIdx.x;
    const int b   = bid >> 6;
    const int c   = bid & 63;
    const int tid = threadIdx.x;
    const int warp = tid >> 5, lane = tid & 31;
    const u32 smem0 = smem_u32_of(sm);
    float* og = out + (size_t)bid * (H_ * W_);
    float* sbias = (float*)(smb + SBIAS_B);

    // ---------------- BN-folded weights -> fp16 [tap][ci][8t], biases ----------------
    if (tid < 160) {
        const int ci = tid / 5, kk = tid - ci * 5;
        const int src = c * 160 + ci * 5 + kk;
        float s0 = gq[c] * rsqrtf(vq[c] + BN_EPS);
        float s1 = gk[c] * rsqrtf(vk[c] + BN_EPS);
        float s2 = gv[c] * rsqrtf(vv[c] + BN_EPS);
        float s3 = gp[c] * rsqrtf(vp[c] + BN_EPS);
        char* wd = smb + W16_BYTE + kk * 512 + ci * 16;
        *(u32*)(wd)      = f16pair(wq[src] * s0, wk[src] * s1);
        *(u32*)(wd + 4)  = f16pair(wv[src] * s2, wp[src] * s3);
        *(u32*)(wd + 8)  = 0u;
        *(u32*)(wd + 12) = 0u;
    }
    if (tid == 0) {
        float s;
        s = gq[c] * rsqrtf(vq[c] + BN_EPS); sbias[0] = bq[c] - mq[c] * s;
        s = gk[c] * rsqrtf(vk[c] + BN_EPS); sbias[1] = bk[c] - mk[c] * s;
        s = gv[c] * rsqrtf(vv[c] + BN_EPS); sbias[2] = bv[c] - mv[c] * s;
        s = gp[c] * rsqrtf(vp[c] + BN_EPS); sbias[3] = bp[c] - mp[c] * s;
    }
    // zero XT halo rows {0,1,514,515} (row = w+2; main stores touch 2..513)
    if (tid < 80) {
        int ri = tid / 20, col = tid % 20;
        int row = (ri < 2) ? ri : (ri + 512);
        *(u32*)(smb + SCR_BYTE + row * 80 + col * 4) = 0u;
    }
    __syncthreads();   // weights + halos + biases visible

    // ---------------- Conv(1x5)+BN+LeakyReLU on tensor cores ----------------
    const float* xb = x + (size_t)b * CIN * H_ * W_;
    const int g  = lane >> 2, tg = lane & 3;

    // persistent weight B-frags: [tap][kstep][2]
    u32 wf[5][2][2];
    #pragma unroll
    for (int k = 0; k < 5; k++)
        #pragma unroll
        for (int ks = 0; ks < 2; ks++) {
            u32 addr = smem0 + W16_BYTE + (u32)(k * 512 + ((ks << 4) + (lane & 15)) * 16);
            asm volatile("ldmatrix.sync.aligned.m8n8.x2.trans.shared.b16 {%0,%1}, [%2];"
                : "=r"(wf[k][ks][0]), "=r"(wf[k][ks][1]) : "r"(addr));
        }

    #pragma unroll 1
    for (int h = 0; h < H_; h++) {
        __syncthreads();   // compute(h-1) done reading XT
        // stage x(h) -> XT[w+2][ci] via stmatrix.x4.trans (no reg prefetch array)
        {
            const int rr = lane >> 2, wq2 = (lane & 3) << 1;
            #pragma unroll
            for (int p = 0; p < 4; p++) {
                int w0s = (warp * 4 + p) << 3;
                u32 q0, q1, q2, q3;
                {
                    const float* px = xb + (size_t)(rr) * (H_ * W_) + h * W_ + w0s + wq2;
                    float2 v0 = *(const float2*)px;
                    float2 v1 = *(const float2*)(px + (size_t)8  * (H_ * W_));
                    float2 v2 = *(const float2*)(px + (size_t)16 * (H_ * W_));
                    float2 v3 = *(const float2*)(px + (size_t)24 * (H_ * W_));
                    q0 = f16pair(v0.x, v0.y);
                    q1 = f16pair(v1.x, v1.y);
                    q2 = f16pair(v2.x, v2.y);
                    q3 = f16pair(v3.x, v3.y);
                }
                u32 addr = smem0 + SCR_BYTE + (u32)((w0s + 2 + (lane & 7)) * 80 + ((lane >> 3) << 4));
                asm volatile("stmatrix.sync.aligned.m8n8.x4.trans.shared.b16 [%0], {%1,%2,%3,%4};"
                    :: "r"(addr), "r"(q0), "r"(q1), "r"(q2), "r"(q3) : "memory");
            }
        }
        __syncthreads();   // XT(h) ready

        // compute: 2 M-tiles x 5 taps x 2 ksteps
        #pragma unroll
        for (int mt = 0; mt < 2; mt++) {
            const int w0 = warp * 32 + mt * 16;
            float c0 = 0.f, c1 = 0.f, c2 = 0.f, c3 = 0.f;
            #pragma unroll
            for (int tap = 0; tap < 5; tap++)
                #pragma unroll
                for (int ks = 0; ks < 2; ks++) {
                    u32 a0, a1, a2, a3;
                    u32 addr = smem0 + SCR_BYTE
                             + (u32)((w0 + tap + (lane & 15)) * 80 + ((lane >> 4) << 4) + (ks << 5));
                    asm volatile("ldmatrix.sync.aligned.m8n8.x4.shared.b16 {%0,%1,%2,%3}, [%4];"
                        : "=r"(a0), "=r"(a1), "=r"(a2), "=r"(a3) : "r"(addr));
                    asm volatile(
                        "mma.sync.aligned.m16n8k16.row.col.f32.f16.f16.f32 "
                        "{%0,%1,%2,%3},{%4,%5,%6,%7},{%8,%9},{%0,%1,%2,%3};"
                        : "+f"(c0), "+f"(c1), "+f"(c2), "+f"(c3)
                        : "r"(a0), "r"(a1), "r"(a2), "r"(a3),
                          "r"(wf[tap][ks][0]), "r"(wf[tap][ks][1]));
                }
            // epilogue: bias + lrelu; scatter Q->Qt, K->K16 swz, V->Vt, PE->gmem
            if (tg < 2) {
                float blo = sbias[2 * tg], bhi = sbias[2 * tg + 1];
                float y00 = c0 + blo, y01 = c1 + bhi, y10 = c2 + blo, y11 = c3 + bhi;
                y00 = fmaxf(y00, LRELU_SLOPE * y00);
                y01 = fmaxf(y01, LRELU_SLOPE * y01);
                y10 = fmaxf(y10, LRELU_SLOPE * y10);
                y11 = fmaxf(y11, LRELU_SLOPE * y11);
                const int w = w0 + g;
                if (tg == 0) {
                    *(u16*)(smb + QT_BYTE + w * 48 + h * 2)       = f16one(y00);
                    *(u16*)(smb + QT_BYTE + (w + 8) * 48 + h * 2) = f16one(y10);
                    *(u16*)(smb + K16_BYTE + h * 1024 + ((u32)(2 * w)       ^ ((u32)((h & 7) << 4)))) = f16one(y01);
                    *(u16*)(smb + K16_BYTE + h * 1024 + ((u32)(2 * (w + 8)) ^ ((u32)((h & 7) << 4)))) = f16one(y11);
                } else {
                    *(u16*)(smb + VT_BYTE + w * 48 + h * 2)       = f16one(y00);
                    *(u16*)(smb + VT_BYTE + (w + 8) * 48 + h * 2) = f16one(y10);
                    og[h * W_ + w]     = y01;   // PE to gmem
                    og[h * W_ + w + 8] = y11;
                }
            }
        }
    }
    __syncthreads();   // conv done; SCR becomes A / VN / SSUM

    // ---------------- Attention: serial per block (2 CTAs/SM provide overlap) -------------
    const int agrp = lane >> 3, alr = lane & 7;
    const int a_voff = (agrp & 1) << 3;
    const int a_roff = (agrp >> 1) << 3;
    float* ssum = (float*)(smb + SSUM_BYTE);

    float acc[2][2][4];
    #pragma unroll
    for (int mi = 0; mi < 2; mi++)
        #pragma unroll
        for (int ni = 0; ni < 2; ni++)
            #pragma unroll
            for (int q = 0; q < 4; q++) acc[mi][ni][q] = 0.0f;

    #pragma unroll 1
    for (int i = 0; i < 16; i++) {
        // ---- produce block i : 8x m16n8k16 f16 MMA, exp, A bf16 store, psums ----
        {
            char* aB = smb + A_BYTE;
            u32 qa[2][4];
            #pragma unroll
            for (int mt = 0; mt < 2; mt++) {
                u32 addr = smem0 + QT_BYTE
                         + (u32)(((i << 5) + mt * 16 + (lane & 15)) * 48 + ((lane >> 4) << 4));
                asm volatile("ldmatrix.sync.aligned.m8n8.x4.shared.b16 {%0,%1,%2,%3}, [%4];"
                    : "=r"(qa[mt][0]), "=r"(qa[mt][1]), "=r"(qa[mt][2]), "=r"(qa[mt][3])
                    : "r"(addr));
            }
            u32 kf[4][2];
            #pragma unroll
            for (int nt = 0; nt < 4; nt++) {
                int h16 = lane & 15;
                u32 v0b = (u32)(((warp << 5) + nt * 8) << 1);
                u32 addr = smem0 + K16_BYTE + (u32)(h16 * 1024) + (v0b ^ ((u32)((h16 & 7) << 4)));
                asm volatile("ldmatrix.sync.aligned.m8n8.x2.trans.shared.b16 {%0,%1}, [%2];"
                    : "=r"(kf[nt][0]), "=r"(kf[nt][1]) : "r"(addr));
            }

            float ps[2][2] = {{0.f, 0.f}, {0.f, 0.f}};
            #pragma unroll
            for (int mt = 0; mt < 2; mt++)
                #pragma unroll
                for (int nt = 0; nt < 4; nt++) {
                    float cf[4] = {0.f, 0.f, 0.f, 0.f};
                    asm volatile(
                        "mma.sync.aligned.m16n8k16.row.col.f32.f16.f16.f32 "
                        "{%0,%1,%2,%3},{%4,%5,%6,%7},{%8,%9},{%0,%1,%2,%3};"
                        : "+f"(cf[0]), "+f"(cf[1]), "+f"(cf[2]), "+f"(cf[3])
                        : "r"(qa[mt][0]), "r"(qa[mt][1]), "r"(qa[mt][2]), "r"(qa[mt][3]),
                          "r"(kf[nt][0]), "r"(kf[nt][1]));
                    float e0 = __expf(cf[0]), e1 = __expf(cf[1]);
                    float e2 = __expf(cf[2]), e3 = __expf(cf[3]);
                    ps[mt][0] += e0 + e1;
                    ps[mt][1] += e2 + e3;
                    const int wlo = mt * 16 + g, whi = wlo + 8;
                    u32 vqb = (u32)((((warp << 5) + nt * 8 + (tg << 1))) << 1);
                    u32 swz = (u32)(g << 4);
                    *(u32*)(aB + wlo * 1024 + (vqb ^ swz)) = bfpair(e0, e1);
                    *(u32*)(aB + whi * 1024 + (vqb ^ swz)) = bfpair(e2, e3);
                }
            #pragma unroll
            for (int mt = 0; mt < 2; mt++)
                #pragma unroll
                for (int q = 0; q < 2; q++) {
                    ps[mt][q] += __shfl_xor_sync(0xffffffffu, ps[mt][q], 1);
                    ps[mt][q] += __shfl_xor_sync(0xffffffffu, ps[mt][q], 2);
                }
            if (tg == 0) {
                #pragma unroll
                for (int mt = 0; mt < 2; mt++) {
                    ssum[(mt * 16 + g) * 20 + warp]     = ps[mt][0];
                    ssum[(mt * 16 + g + 8) * 20 + warp] = ps[mt][1];
                }
            }
        }
        __syncthreads();   // A(i) + psums(i) visible

        // ---- Vn[h][w] = Vt16[wb+w][h] * rinv(w), bf16, 80B row stride ----
        {
            const int wb = i << 5;
            const int h2 = tid >> 5, r = lane;
            const float* pp = ssum + r * 20;
            float4 s0 = *(const float4*)(pp);
            float4 s1 = *(const float4*)(pp + 4);
            float4 s2 = *(const float4*)(pp + 8);
            float4 s3 = *(const float4*)(pp + 12);
            float sum = ((s0.x + s0.y) + (s0.z + s0.w)) + ((s1.x + s1.y) + (s1.z + s1.w))
                      + ((s2.x + s2.y) + (s2.z + s2.w)) + ((s3.x + s3.y) + (s3.z + s3.w));
            u16 vraw = *(const u16*)(smb + VT_BYTE + (wb + r) * 48 + h2 * 2);
            float vn = f16tof32(vraw) * __fdividef(1.0f, sum);
            *(u16*)(smb + VN_BYTE + h2 * 80 + r * 2) = (u16)(bfpair(vn, 0.0f) & 0xFFFFu);
        }
        __syncthreads();   // Vn(i) visible

        // ---- consume block i : D[v][h] += A'[v][w] * Vn[w][h] ----
        {
            const u32 ab = smem0 + A_BYTE;
            const u32 bb = smem0 + VN_BYTE;
            u32 bfr[2][2][2];
            #pragma unroll
            for (int ni = 0; ni < 2; ni++)
                #pragma unroll
                for (int ks = 0; ks < 2; ks++) {
                    u32 addr = bb + (u32)((ni * 8 + (lane & 7)) * 80 + ks * 32 + ((lane >> 3) & 1) * 16);
                    asm volatile("ldmatrix.sync.aligned.m8n8.x2.shared.b16 {%0,%1}, [%2];"
                        : "=r"(bfr[ni][ks][0]), "=r"(bfr[ni][ks][1]) : "r"(addr));
                }
            #pragma unroll
            for (int mi = 0; mi < 2; mi++) {
                u32 af[2][4];
                #pragma unroll
                for (int ks = 0; ks < 2; ks++) {
                    const int r  = ks * 16 + a_roff + alr;
                    const int vb = (warp << 5) + (mi << 4) + a_voff;
                    u32 addr = ab + (u32)(r * 1024 + (((u32)(vb * 2)) ^ ((u32)(alr << 4))));
                    asm volatile("ldmatrix.sync.aligned.m8n8.x4.trans.shared.b16 {%0,%1,%2,%3}, [%4];"
                        : "=r"(af[ks][0]), "=r"(af[ks][1]), "=r"(af[ks][2]), "=r"(af[ks][3])
                        : "r"(addr));
                }
                #pragma unroll
                for (int ni = 0; ni < 2; ni++)
                    #pragma unroll
                    for (int ks = 0; ks < 2; ks++)
                        asm volatile(
                            "mma.sync.aligned.m16n8k16.row.col.f32.bf16.bf16.f32 "
                            "{%0,%1,%2,%3},{%4,%5,%6,%7},{%8,%9},{%0,%1,%2,%3};"
                            : "+f"(acc[mi][ni][0]), "+f"(acc[mi][ni][1]),
                              "+f"(acc[mi][ni][2]), "+f"(acc[mi][ni][3])
                            : "r"(af[ks][0]), "r"(af[ks][1]), "r"(af[ks][2]), "r"(af[ks][3]),
                              "r"(bfr[ni][ks][0]), "r"(bfr[ni][ks][1]));
            }
        }
        __syncthreads();   // consume(i) done; A free for produce(i+1)
    }

    // ---------------- Epilogue: out = D + PE (PE read back from gmem) ----------------
    {
        const int vb = (warp << 5) + (lane >> 2);
        const int hb2 = (lane & 3) << 1;
        #pragma unroll
        for (int mi = 0; mi < 2; mi++)
            #pragma unroll
            for (int ni = 0; ni < 2; ni++) {
                const int v = vb + (mi << 4);
                const int h = hb2 + (ni << 3);
                float p0 = og[h * W_ + v];
                float p1 = og[(h + 1) * W_ + v];
                float p2 = og[h * W_ + v + 8];
                float p3 = og[(h + 1) * W_ + v + 8];
                og[h * W_ + v]           = acc[mi][ni][0] + p0;
                og[(h + 1) * W_ + v]     = acc[mi][ni][1] + p1;
                og[h * W_ + v + 8]       = acc[mi][ni][2] + p2;
                og[(h + 1) * W_ + v + 8] = acc[mi][ni][3] + p3;
            }
    }
}

extern "C" void kernel_launch(void* const* d_in, const int* in_sizes, int n_in,
                              void* d_out, int out_size)
{
    cudaFuncSetAttribute(conv_attn_fused_kernel,
                         cudaFuncAttributeMaxDynamicSharedMemorySize, SMEM_BYTES);

    const float* x  = (const float*)d_in[0];
    const float* wq = (const float*)d_in[1];
    const float* gq = (const float*)d_in[2];
    const float* bq = (const float*)d_in[3];
    const float* mq = (const float*)d_in[4];
    const float* vq = (const float*)d_in[5];
    const float* wk = (const float*)d_in[6];
    const float* gk = (const float*)d_in[7];
    const float* bk = (const float*)d_in[8];
    const float* mk = (const float*)d_in[9];
    const float* vk = (const float*)d_in[10];
    const float* wv = (const float*)d_in[11];
    const float* gv = (const float*)d_in[12];
    const float* bv = (const float*)d_in[13];
    const float* mv = (const float*)d_in[14];
    const float* vv = (const float*)d_in[15];
    const float* wp = (const float*)d_in[16];
    const float* gp = (const float*)d_in[17];
    const float* bp = (const float*)d_in[18];
    const float* mp = (const float*)d_in[19];
    const float* vp = (const float*)d_in[20];

    conv_attn_fused_kernel<<<B_ * COUT, 512, SMEM_BYTES>>>(
        x,
        wq, gq, bq, mq, vq,
        wk, gk, bk, mk, vk,
        wv, gv, bv, mv, vv,
        wp, gp, bp, mp, vp,
        (float*)d_out);
}